// round 4
// baseline (speedup 1.0000x reference)
#include <cuda_runtime.h>
#include <cuda_bf16.h>

// ---------------------------------------------------------------------------
// HashEncoder (instant-ngp style), GB300 sm_103a
//   B points (x,y,z in [0,1]) -> [B, 16 levels * 2 feats] fp32
//   All 16 levels take the spatial-hash path (table sizes rounded down to 8).
//
// R3: branchless pair-gather on ALL levels.
//   - x prime is 1, so the two x-adjacent corners satisfy idx1 = idx0 ^ 1
//     when gx is even; since every table size is even, the pairing survives
//     both the 2^19 mask and the non-pow2 modulo ((h^1)%m == (h%m)^1).
//   - The aligned float4 at (idx0 & ~1) ALWAYS contains the even-x corner;
//     it also contains the odd-x corner iff gx is even.
//   => 4 unconditional LDG.128 + 4 LDG.64 predicated on gx odd.
//      No divergent branch, 8 load issues/thread instead of 12.
// ---------------------------------------------------------------------------

#define TP       16          // points per block
#define NLEVELS  16
#define NTHREADS (TP * NLEVELS)

__constant__ unsigned c_off[NLEVELS] = {
    0u,        4912u,     40848u,    315472u,
    839760u,   1364048u,  1888336u,  2412624u,
    2936912u,  3461200u,  3985488u,  4509776u,
    5034064u,  5558352u,  6082640u,  6606928u
};

__global__ __launch_bounds__(NTHREADS)
void hash_encoder_kernel(const float* __restrict__ xyz,
                         const float2* __restrict__ emb,
                         float2* __restrict__ out,
                         int B)
{
    __shared__ float  sxyz[TP * 3];
    __shared__ float2 sres[TP][NLEVELS + 1];   // +1 pad: kill bank conflicts

    const int tid   = threadIdx.x;
    const int level = tid >> 4;      // 0..15
    const int p     = tid & 15;      // point within block
    const long long base = (long long)blockIdx.x * TP;

    // stage this block's 16 points (48 floats), coalesced
    if (tid < TP * 3) {
        long long g = base * 3 + tid;
        sxyz[tid] = (g < (long long)B * 3) ? xyz[g] : 0.0f;
    }
    __syncthreads();

    const float x = sxyz[p * 3 + 0];
    const float y = sxyz[p * 3 + 1];
    const float z = sxyz[p * 3 + 2];

    // scale = exp2(level)*16 - 1  (exact in fp32)
    const float scale = (float)(16u << level) - 1.0f;

    const float px = fmaf(x, scale, 0.5f);
    const float py = fmaf(y, scale, 0.5f);
    const float pz = fmaf(z, scale, 0.5f);
    const float gx_f = floorf(px), gy_f = floorf(py), gz_f = floorf(pz);
    const float fx = px - gx_f, fy = py - gy_f, fz = pz - gz_f;
    const unsigned gx = (unsigned)gx_f;
    const unsigned gy = (unsigned)gy_f;
    const unsigned gz = (unsigned)gz_f;

    // spatial hash: idx = (x*1) ^ (y*2654435761) ^ (z*805459861)  (u32 wrap)
    const unsigned hx0 = gx;
    const unsigned hx1 = gx + 1u;
    const unsigned hy0 = gy * 2654435761u;
    const unsigned hy1 = (gy + 1u) * 2654435761u;
    const unsigned hz0 = gz * 805459861u;
    const unsigned hz1 = (gz + 1u) * 805459861u;

    // corner order: bit0 = x, bit1 = y, bit2 = z
    unsigned idx[8];
    idx[0] = hx0 ^ hy0 ^ hz0;
    idx[1] = hx1 ^ hy0 ^ hz0;
    idx[2] = hx0 ^ hy1 ^ hz0;
    idx[3] = hx1 ^ hy1 ^ hz0;
    idx[4] = hx0 ^ hy0 ^ hz1;
    idx[5] = hx1 ^ hy0 ^ hz1;
    idx[6] = hx0 ^ hy1 ^ hz1;
    idx[7] = hx1 ^ hy1 ^ hz1;

    // per-level index reduction (warp-uniform except warp 1: levels 2|3)
    if (level >= 3) {
        #pragma unroll
        for (int c = 0; c < 8; c++) idx[c] &= 524287u;       // 2^19 mask
    } else if (level == 2) {
        #pragma unroll
        for (int c = 0; c < 8; c++) idx[c] %= 274624u;
    } else if (level == 1) {
        #pragma unroll
        for (int c = 0; c < 8; c++) idx[c] %= 35936u;
    } else {
        #pragma unroll
        for (int c = 0; c < 8; c++) idx[c] %= 4912u;
    }

    const float2* __restrict__ tab = emb + c_off[level];
    const bool gx_even = ((gx & 1u) == 0u);

    // branchless pair-gather: 4x LDG.128 always + 4x LDG.64 predicated on odd gx
    float2 v[8];
    #pragma unroll
    for (int pr = 0; pr < 4; pr++) {
        const unsigned i0 = idx[2 * pr];       // even-x corner
        const unsigned i1 = idx[2 * pr + 1];   // odd-x corner
        const float4 q = __ldg((const float4*)(tab + (i0 & ~1u)));
        const float2 lo = make_float2(q.x, q.y);
        const float2 hi = make_float2(q.z, q.w);
        const bool o = (i0 & 1u) != 0u;
        v[2 * pr] = o ? hi : lo;               // always valid
        float2 b  = o ? lo : hi;               // pair-mate, valid iff gx even
        if (!gx_even) b = __ldg(&tab[i1]);     // predicated single load
        v[2 * pr + 1] = b;
    }

    const float wx0 = 1.0f - fx, wy0 = 1.0f - fy, wz0 = 1.0f - fz;
    float w[8];
    w[0] = (wx0 * wy0) * wz0;
    w[1] = (fx  * wy0) * wz0;
    w[2] = (wx0 * fy ) * wz0;
    w[3] = (fx  * fy ) * wz0;
    w[4] = (wx0 * wy0) * fz;
    w[5] = (fx  * wy0) * fz;
    w[6] = (wx0 * fy ) * fz;
    w[7] = (fx  * fy ) * fz;

    float rx = 0.0f, ry = 0.0f;
    #pragma unroll
    for (int c = 0; c < 8; c++) {
        rx = fmaf(w[c], v[c].x, rx);
        ry = fmaf(w[c], v[c].y, ry);
    }

    sres[p][level] = make_float2(rx, ry);
    __syncthreads();

    // coalesced writeback: block tile = 16 points x 16 float2, contiguous
    const int pp = tid >> 4;
    const int ll = tid & 15;
    if (base + pp < (long long)B) {
        out[base * NLEVELS + tid] = sres[pp][ll];
    }
}

extern "C" void kernel_launch(void* const* d_in, const int* in_sizes, int n_in,
                              void* d_out, int out_size)
{
    const float*  xyz = (const float*)d_in[0];
    const float2* emb = (const float2*)d_in[1];
    // d_in[2] = normalize flag (0) -> raw coordinates path; ignored.

    const int B = in_sizes[0] / 3;
    const int blocks = (B + TP - 1) / TP;

    hash_encoder_kernel<<<blocks, NTHREADS>>>(xyz, emb, (float2*)d_out, B);
}

// round 5
// speedup vs baseline: 1.0774x; 1.0774x over previous
#include <cuda_runtime.h>
#include <cuda_bf16.h>

// ---------------------------------------------------------------------------
// HashEncoder (instant-ngp style), GB300 sm_103a
//   B points (x,y,z in [0,1]) -> [B, 16 levels * 2 feats] fp32
//   All 16 levels take the spatial-hash path (table sizes rounded down to 8).
//
// R5: R2's proven gather structure (divergent even/odd-gx branch, each arm
//     issues only its minimal loads: 4x LDG.128 vs 8x LDG.64), plus
//     one-level-per-warp layout (512 thr = 32 points x 16 levels) so the
//     per-level modulo/offset/scale paths are warp-uniform instead of
//     2-way divergent in every warp.
// ---------------------------------------------------------------------------

#define TP       32          // points per block
#define NLEVELS  16
#define NTHREADS (TP * NLEVELS)   // 512

__constant__ unsigned c_off[NLEVELS] = {
    0u,        4912u,     40848u,    315472u,
    839760u,   1364048u,  1888336u,  2412624u,
    2936912u,  3461200u,  3985488u,  4509776u,
    5034064u,  5558352u,  6082640u,  6606928u
};

__global__ __launch_bounds__(NTHREADS)
void hash_encoder_kernel(const float* __restrict__ xyz,
                         const float2* __restrict__ emb,
                         float2* __restrict__ out,
                         int B)
{
    __shared__ float  sxyz[TP * 3];
    __shared__ float2 sres[TP][NLEVELS + 1];   // +1 pad: conflict-free transpose

    const int tid   = threadIdx.x;
    const int level = tid >> 5;      // warp id == level (warp-uniform)
    const int p     = tid & 31;      // point within block
    const long long base = (long long)blockIdx.x * TP;

    // stage this block's 32 points (96 floats), coalesced
    if (tid < TP * 3) {
        long long g = base * 3 + tid;
        sxyz[tid] = (g < (long long)B * 3) ? xyz[g] : 0.0f;
    }
    __syncthreads();

    const float x = sxyz[p * 3 + 0];
    const float y = sxyz[p * 3 + 1];
    const float z = sxyz[p * 3 + 2];

    // scale = exp2(level)*16 - 1  (exact in fp32; warp-uniform)
    const float scale = (float)(16u << level) - 1.0f;

    const float px = fmaf(x, scale, 0.5f);
    const float py = fmaf(y, scale, 0.5f);
    const float pz = fmaf(z, scale, 0.5f);
    const float gx_f = floorf(px), gy_f = floorf(py), gz_f = floorf(pz);
    const float fx = px - gx_f, fy = py - gy_f, fz = pz - gz_f;
    const unsigned gx = (unsigned)gx_f;
    const unsigned gy = (unsigned)gy_f;
    const unsigned gz = (unsigned)gz_f;

    // spatial hash: idx = (x*1) ^ (y*2654435761) ^ (z*805459861)  (u32 wrap)
    const unsigned hx0 = gx;
    const unsigned hx1 = gx + 1u;
    const unsigned hy0 = gy * 2654435761u;
    const unsigned hy1 = (gy + 1u) * 2654435761u;
    const unsigned hz0 = gz * 805459861u;
    const unsigned hz1 = (gz + 1u) * 805459861u;

    // corner order: bit0 = x, bit1 = y, bit2 = z
    unsigned idx[8];
    idx[0] = hx0 ^ hy0 ^ hz0;
    idx[1] = hx1 ^ hy0 ^ hz0;
    idx[2] = hx0 ^ hy1 ^ hz0;
    idx[3] = hx1 ^ hy1 ^ hz0;
    idx[4] = hx0 ^ hy0 ^ hz1;
    idx[5] = hx1 ^ hy0 ^ hz1;
    idx[6] = hx0 ^ hy1 ^ hz1;
    idx[7] = hx1 ^ hy1 ^ hz1;

    // per-level index reduction — warp-uniform branch now
    if (level >= 3) {
        #pragma unroll
        for (int c = 0; c < 8; c++) idx[c] &= 524287u;       // 2^19 mask
    } else if (level == 2) {
        #pragma unroll
        for (int c = 0; c < 8; c++) idx[c] %= 274624u;
    } else if (level == 1) {
        #pragma unroll
        for (int c = 0; c < 8; c++) idx[c] %= 35936u;
    } else {
        #pragma unroll
        for (int c = 0; c < 8; c++) idx[c] %= 4912u;
    }

    const float2* __restrict__ tab = emb + c_off[level];
    float2 v[8];

    // R2 gather structure: per-lane parity branch; each arm issues only its
    // minimal loads (masked-off lanes generate no L1 wavefronts).
    if ((gx & 1u) == 0u) {
        // gx even -> idx[2p+1] == idx[2p]^1: each x-pair sits in one aligned
        // {2k,2k+1} float4 (one 32B sector). 4x LDG.128.
        #pragma unroll
        for (int pr = 0; pr < 4; pr++) {
            const unsigned i0 = idx[2 * pr];
            const float4 q = __ldg((const float4*)(tab + (i0 & ~1u)));
            const float2 lo = make_float2(q.x, q.y);
            const float2 hi = make_float2(q.z, q.w);
            const bool o = (i0 & 1u) != 0u;
            v[2 * pr]     = o ? hi : lo;
            v[2 * pr + 1] = o ? lo : hi;
        }
    } else {
        #pragma unroll
        for (int c = 0; c < 8; c++) v[c] = __ldg(&tab[idx[c]]);
    }

    const float wx0 = 1.0f - fx, wy0 = 1.0f - fy, wz0 = 1.0f - fz;
    float w[8];
    w[0] = (wx0 * wy0) * wz0;
    w[1] = (fx  * wy0) * wz0;
    w[2] = (wx0 * fy ) * wz0;
    w[3] = (fx  * fy ) * wz0;
    w[4] = (wx0 * wy0) * fz;
    w[5] = (fx  * wy0) * fz;
    w[6] = (wx0 * fy ) * fz;
    w[7] = (fx  * fy ) * fz;

    float rx = 0.0f, ry = 0.0f;
    #pragma unroll
    for (int c = 0; c < 8; c++) {
        rx = fmaf(w[c], v[c].x, rx);
        ry = fmaf(w[c], v[c].y, ry);
    }

    sres[p][level] = make_float2(rx, ry);
    __syncthreads();

    // coalesced writeback: block tile = 32 points x 16 float2, contiguous
    const int pp = tid >> 4;     // point for writeback (0..31)
    const int ll = tid & 15;     // level for writeback
    if (base + pp < (long long)B) {
        out[base * NLEVELS + tid] = sres[pp][ll];
    }
}

extern "C" void kernel_launch(void* const* d_in, const int* in_sizes, int n_in,
                              void* d_out, int out_size)
{
    const float*  xyz = (const float*)d_in[0];
    const float2* emb = (const float2*)d_in[1];
    // d_in[2] = normalize flag (0) -> raw coordinates path; ignored.

    const int B = in_sizes[0] / 3;
    const int blocks = (B + TP - 1) / TP;

    hash_encoder_kernel<<<blocks, NTHREADS>>>(xyz, emb, (float2*)d_out, B);
}

// round 6
// speedup vs baseline: 1.1401x; 1.0581x over previous
#include <cuda_runtime.h>
#include <cuda_bf16.h>

// ---------------------------------------------------------------------------
// HashEncoder (instant-ngp style), GB300 sm_103a
//   B points (x,y,z in [0,1]) -> [B, 16 levels * 2 feats] fp32
//   All 16 levels take the spatial-hash path (table sizes rounded down to 8).
//
// R6: exactly R2's measured-fastest structure (256 thr, level = tid>>4,
//     divergent even/odd-gx gather at level>=3), with the float4 pair-merge
//     additionally applied to levels 0-2: table sizes are even, so
//     (h^1) % m == (h%m) ^ 1 for even h — the x-pair stays an aligned
//     {2k,2k+1} float4 after the modulo. Cuts per-point L1 lane-accesses
//     102 -> 96.
// ---------------------------------------------------------------------------

#define TP       16          // points per block
#define NLEVELS  16
#define NTHREADS (TP * NLEVELS)   // 256

__constant__ unsigned c_off[NLEVELS] = {
    0u,        4912u,     40848u,    315472u,
    839760u,   1364048u,  1888336u,  2412624u,
    2936912u,  3461200u,  3985488u,  4509776u,
    5034064u,  5558352u,  6082640u,  6606928u
};

// even-gx fast path: 4 aligned float4 loads cover all 8 corners
__device__ __forceinline__ void gather_pairs(const float2* __restrict__ tab,
                                             const unsigned* idx, float2* v)
{
    #pragma unroll
    for (int pr = 0; pr < 4; pr++) {
        const unsigned i0 = idx[2 * pr];
        const float4 q = __ldg((const float4*)(tab + (i0 & ~1u)));
        const float2 lo = make_float2(q.x, q.y);
        const float2 hi = make_float2(q.z, q.w);
        const bool o = (i0 & 1u) != 0u;
        v[2 * pr]     = o ? hi : lo;
        v[2 * pr + 1] = o ? lo : hi;
    }
}

__device__ __forceinline__ void gather_single(const float2* __restrict__ tab,
                                              const unsigned* idx, float2* v)
{
    #pragma unroll
    for (int c = 0; c < 8; c++) v[c] = __ldg(&tab[idx[c]]);
}

__global__ __launch_bounds__(NTHREADS)
void hash_encoder_kernel(const float* __restrict__ xyz,
                         const float2* __restrict__ emb,
                         float2* __restrict__ out,
                         int B)
{
    __shared__ float  sxyz[TP * 3];
    __shared__ float2 sres[TP][NLEVELS + 1];   // +1 pad: conflict-free transpose

    const int tid   = threadIdx.x;
    const int level = tid >> 4;      // 0..15 (each warp spans 2 levels)
    const int p     = tid & 15;      // point within block
    const long long base = (long long)blockIdx.x * TP;

    // stage this block's 16 points (48 floats), coalesced
    if (tid < TP * 3) {
        long long g = base * 3 + tid;
        sxyz[tid] = (g < (long long)B * 3) ? xyz[g] : 0.0f;
    }
    __syncthreads();

    const float x = sxyz[p * 3 + 0];
    const float y = sxyz[p * 3 + 1];
    const float z = sxyz[p * 3 + 2];

    // scale = exp2(level)*16 - 1  (exact in fp32)
    const float scale = (float)(16u << level) - 1.0f;

    const float px = fmaf(x, scale, 0.5f);
    const float py = fmaf(y, scale, 0.5f);
    const float pz = fmaf(z, scale, 0.5f);
    const float gx_f = floorf(px), gy_f = floorf(py), gz_f = floorf(pz);
    const float fx = px - gx_f, fy = py - gy_f, fz = pz - gz_f;
    const unsigned gx = (unsigned)gx_f;
    const unsigned gy = (unsigned)gy_f;
    const unsigned gz = (unsigned)gz_f;

    // spatial hash: idx = (x*1) ^ (y*2654435761) ^ (z*805459861)  (u32 wrap)
    const unsigned hx0 = gx;
    const unsigned hx1 = gx + 1u;
    const unsigned hy0 = gy * 2654435761u;
    const unsigned hy1 = (gy + 1u) * 2654435761u;
    const unsigned hz0 = gz * 805459861u;
    const unsigned hz1 = (gz + 1u) * 805459861u;

    // corner order: bit0 = x, bit1 = y, bit2 = z
    unsigned idx[8];
    idx[0] = hx0 ^ hy0 ^ hz0;
    idx[1] = hx1 ^ hy0 ^ hz0;
    idx[2] = hx0 ^ hy1 ^ hz0;
    idx[3] = hx1 ^ hy1 ^ hz0;
    idx[4] = hx0 ^ hy0 ^ hz1;
    idx[5] = hx1 ^ hy0 ^ hz1;
    idx[6] = hx0 ^ hy1 ^ hz1;
    idx[7] = hx1 ^ hy1 ^ hz1;

    const bool gx_even = ((gx & 1u) == 0u);
    const float2* __restrict__ tab = emb + c_off[level];
    float2 v[8];

    if (level >= 3) {
        #pragma unroll
        for (int c = 0; c < 8; c++) idx[c] &= 524287u;       // 2^19 mask
        if (gx_even) gather_pairs(tab, idx, v);
        else         gather_single(tab, idx, v);
    } else {
        // even table sizes -> parity survives the modulo; pairing still valid
        if (level == 2) {
            #pragma unroll
            for (int c = 0; c < 8; c++) idx[c] %= 274624u;
        } else if (level == 1) {
            #pragma unroll
            for (int c = 0; c < 8; c++) idx[c] %= 35936u;
        } else {
            #pragma unroll
            for (int c = 0; c < 8; c++) idx[c] %= 4912u;
        }
        if (gx_even) gather_pairs(tab, idx, v);
        else         gather_single(tab, idx, v);
    }

    const float wx0 = 1.0f - fx, wy0 = 1.0f - fy, wz0 = 1.0f - fz;
    float w[8];
    w[0] = (wx0 * wy0) * wz0;
    w[1] = (fx  * wy0) * wz0;
    w[2] = (wx0 * fy ) * wz0;
    w[3] = (fx  * fy ) * wz0;
    w[4] = (wx0 * wy0) * fz;
    w[5] = (fx  * wy0) * fz;
    w[6] = (wx0 * fy ) * fz;
    w[7] = (fx  * fy ) * fz;

    float rx = 0.0f, ry = 0.0f;
    #pragma unroll
    for (int c = 0; c < 8; c++) {
        rx = fmaf(w[c], v[c].x, rx);
        ry = fmaf(w[c], v[c].y, ry);
    }

    sres[p][level] = make_float2(rx, ry);
    __syncthreads();

    // coalesced writeback: block tile = 16 points x 16 float2, contiguous
    const int pp = tid >> 4;
    const int ll = tid & 15;
    if (base + pp < (long long)B) {
        out[base * NLEVELS + tid] = sres[pp][ll];
    }
}

extern "C" void kernel_launch(void* const* d_in, const int* in_sizes, int n_in,
                              void* d_out, int out_size)
{
    const float*  xyz = (const float*)d_in[0];
    const float2* emb = (const float2*)d_in[1];
    // d_in[2] = normalize flag (0) -> raw coordinates path; ignored.

    const int B = in_sizes[0] / 3;
    const int blocks = (B + TP - 1) / TP;

    hash_encoder_kernel<<<blocks, NTHREADS>>>(xyz, emb, (float2*)d_out, B);
}